// round 1
// baseline (speedup 1.0000x reference)
#include <cuda_runtime.h>
#include <math.h>

#define NB   4
#define NCLS 3
#define FH   256       // feature H=W
#define CH   128       // coarse H=W
#define NIN  128
#define KIN  131
#define PPB  8192      // points per batch
#define PTOT 32768     // 4 * 8192
#define KEYSTRIDE 262144

// ---------------- scratch (device globals; no allocations allowed) ----------------
__device__ float        g_featT[(size_t)NB*FH*FH*NIN];   // NHWC features, 134MB
__device__ float        g_sem256[NB*NCLS*256*256];       // step-1 refined sem
__device__ unsigned int g_keys[NB*KEYSTRIDE];            // ordered uncertainty keys
__device__ unsigned int g_hist[NB*65536];                // radix histograms
__device__ int          g_dig[NB][4];                    // resolved 16-bit digits
__device__ int          g_kRem[NB];
__device__ int          g_selCount[NB];
__device__ int          g_idx[PTOT];                     // selected flat indices
__device__ float        g_Xa[(size_t)KIN*PTOT];          // MLP ping
__device__ float        g_Xb[(size_t)KIN*PTOT];          // MLP pong

__device__ __forceinline__ unsigned int fkey(float f) {
    unsigned int u = __float_as_uint(f);
    return (u & 0x80000000u) ? ~u : (u | 0x80000000u);  // larger float -> larger uint
}

// ---------------- features NCHW -> NHWC ----------------
__global__ void transpose_kernel(const float* __restrict__ f) {
    __shared__ float tile[32][33];
    int n = blockIdx.z;
    int pix0 = blockIdx.x * 32;
    int c0   = blockIdx.y * 32;
    int tx = threadIdx.x, ty = threadIdx.y;   // 32 x 8
    #pragma unroll
    for (int i = ty; i < 32; i += 8)
        tile[i][tx] = f[(size_t)(n*NIN + c0 + i)*(FH*FH) + pix0 + tx];
    __syncthreads();
    #pragma unroll
    for (int i = ty; i < 32; i += 8)
        g_featT[(size_t)(n*(FH*FH) + pix0 + i)*NIN + c0 + tx] = tile[tx][i];
}

// ---------------- 2x bilinear upsample (half-pixel, edge-renormalized) + uncertainty keys ----------------
__global__ void upsample_unc(const float* __restrict__ in, float* __restrict__ out, int Hin) {
    int W = 2*Hin; int HW = W*W;
    int gid = blockIdx.x*blockDim.x + threadIdx.x;
    if (gid >= NB*HW) return;
    int n = gid / HW; int pix = gid - n*HW;
    int y = pix / W;  int x = pix - y*W;
    int y0 = (y - 1) >> 1, x0 = (x - 1) >> 1;       // floor((i+0.5)/2 - 0.5)
    float wy1 = (y & 1) ? 0.25f : 0.75f;
    float wx1 = (x & 1) ? 0.25f : 0.75f;
    int y1 = y0 + 1, x1 = x0 + 1;
    int xa = (x0 < 0) ? 0 : x0;
    int xb = (x1 > Hin-1) ? Hin-1 : x1;
    float v[NCLS];
    #pragma unroll
    for (int c = 0; c < NCLS; c++) {
        const float* p = in + (size_t)(n*NCLS + c)*Hin*Hin;
        float colA, colB;
        if (y0 < 0)              { colA = p[xa];                 colB = p[xb]; }
        else if (y1 > Hin - 1)   { colA = p[(Hin-1)*Hin + xa];   colB = p[(Hin-1)*Hin + xb]; }
        else {
            colA = (1.f - wy1)*p[y0*Hin + xa] + wy1*p[y1*Hin + xa];
            colB = (1.f - wy1)*p[y0*Hin + xb] + wy1*p[y1*Hin + xb];
        }
        float vv;
        if (x0 < 0)            vv = colA;
        else if (x1 > Hin - 1) vv = colB;
        else                   vv = (1.f - wx1)*colA + wx1*colB;
        v[c] = vv;
        out[(size_t)(n*NCLS + c)*HW + pix] = vv;
    }
    float hi = fmaxf(v[0], v[1]), lo = fminf(v[0], v[1]);
    float m1 = fmaxf(hi, v[2]);
    float m2 = fmaxf(lo, fminf(hi, v[2]));
    g_keys[n*KEYSTRIDE + pix] = fkey(m2 - m1);   // top2 - top1 (<=0)
}

// ---------------- exact top-8192 per batch: 4x16-bit radix select on (key, ~index) ----------------
__global__ void select_init() {
    int i = blockIdx.x*blockDim.x + threadIdx.x;
    int stride = gridDim.x*blockDim.x;
    for (int j = i; j < NB*65536; j += stride) g_hist[j] = 0;
    if (i < NB) { g_kRem[i] = PPB; g_selCount[i] = 0; }
}

__global__ void hist_kernel(int pass, int HW) {
    int n = blockIdx.y;
    __shared__ unsigned int sdig[4];
    if (threadIdx.x < 4) sdig[threadIdx.x] = (unsigned)g_dig[n][threadIdx.x];
    __syncthreads();
    int stride = gridDim.x*blockDim.x;
    for (int i = blockIdx.x*blockDim.x + threadIdx.x; i < HW; i += stride) {
        unsigned int key = g_keys[n*KEYSTRIDE + i];
        unsigned int lo  = ~(unsigned int)i;
        unsigned int dd[4] = {key >> 16, key & 0xFFFFu, lo >> 16, lo & 0xFFFFu};
        bool ok = true;
        #pragma unroll
        for (int q = 0; q < 3; q++) if (q < pass) ok = ok && (dd[q] == sdig[q]);
        if (ok) atomicAdd(&g_hist[n*65536 + dd[pass]], 1u);
    }
}

__global__ void resolve_kernel(int pass) {
    int n = blockIdx.x, t = threadIdx.x;    // 4 blocks x 256 threads
    unsigned int* hist = g_hist + n*65536;
    __shared__ unsigned int chunkSum[256];
    __shared__ unsigned int csum[257];
    int base = 65535 - (t << 8);            // descending chunks of 256 digits
    unsigned int s = 0;
    #pragma unroll 4
    for (int j = 0; j < 256; j++) s += hist[base - j];
    chunkSum[t] = s;
    __syncthreads();
    if (t == 0) {
        unsigned int c = 0;
        for (int i = 0; i < 256; i++) { csum[i] = c; c += chunkSum[i]; }
        csum[256] = c;
    }
    __syncthreads();
    unsigned int kRem = (unsigned)g_kRem[n];
    if (csum[t] < kRem && kRem <= csum[t+1]) {   // unique crossing thread
        unsigned int c = csum[t];
        for (int j = 0; j < 256; j++) {
            unsigned int h = hist[base - j];
            if (c + h >= kRem) {
                g_dig[n][pass] = base - j;
                g_kRem[n] = (int)(kRem - c);
                break;
            }
            c += h;
        }
    }
    __syncthreads();
    for (int j = t; j < 65536; j += 256) hist[j] = 0;   // clear for next pass
    if (pass == 3 && t == 0) g_selCount[n] = 0;
}

__global__ void select_kernel(int HW) {
    int n = blockIdx.y;
    unsigned int thrHi = ((unsigned)g_dig[n][0] << 16) | (unsigned)g_dig[n][1];
    unsigned int thrLo = ((unsigned)g_dig[n][2] << 16) | (unsigned)g_dig[n][3];
    int stride = gridDim.x*blockDim.x;
    for (int i = blockIdx.x*blockDim.x + threadIdx.x; i < HW; i += stride) {
        unsigned int key = g_keys[n*KEYSTRIDE + i];
        if (key < thrHi) continue;
        unsigned int lo = ~(unsigned int)i;
        if (key > thrHi || lo >= thrLo) {          // composite >= kth-largest (all distinct)
            int pos = atomicAdd(&g_selCount[n], 1);
            if (pos < PPB) g_idx[n*PPB + pos] = i;
        }
    }
}

// ---------------- gather: bilinear sample features (NHWC) + coarse, pack X [131][PTOT] ----------------
__global__ void gather_kernel(const float* __restrict__ coarse, int gridW) {
    __shared__ float tile[KIN][33];
    __shared__ int   sx0[32], sy0[32];
    __shared__ float sw0[32], sw1[32], sw2[32], sw3[32];
    __shared__ float spx[32], spy[32];
    int pBase = blockIdx.x * 32;        // 32 points per block, never straddles a batch
    int tid = threadIdx.x;              // 128 threads
    int n = pBase >> 13;
    if (tid < 32) {
        int id = g_idx[pBase + tid];
        float px = ((float)(id % gridW) + 0.5f) / (float)gridW;
        float py = ((float)(id / gridW) + 0.5f) / (float)gridW;
        spx[tid] = px; spy[tid] = py;
        float fx = px * 256.f - 0.5f, fy = py * 256.f - 0.5f;
        float fx0 = floorf(fx), fy0 = floorf(fy);
        float wx1 = fx - fx0, wy1 = fy - fy0;
        sx0[tid] = (int)fx0; sy0[tid] = (int)fy0;
        sw0[tid] = (1.f-wx1)*(1.f-wy1);
        sw1[tid] = wx1*(1.f-wy1);
        sw2[tid] = (1.f-wx1)*wy1;
        sw3[tid] = wx1*wy1;
    }
    __syncthreads();
    int c = tid;   // channel 0..127
    const float* base = g_featT + (size_t)n*FH*FH*NIN;
    for (int j = 0; j < 32; j++) {
        int x0 = sx0[j], y0 = sy0[j];
        float acc = 0.f;   // corner order matches reference: 00, 10, 01, 11; zeros padding
        if (x0 >= 0   && y0 >= 0  ) acc += sw0[j]*base[((y0  )*FH + x0  )*NIN + c];
        if (x0+1 < FH && y0 >= 0  ) acc += sw1[j]*base[((y0  )*FH + x0+1)*NIN + c];
        if (x0 >= 0   && y0+1 < FH) acc += sw2[j]*base[((y0+1)*FH + x0  )*NIN + c];
        if (x0+1 < FH && y0+1 < FH) acc += sw3[j]*base[((y0+1)*FH + x0+1)*NIN + c];
        tile[c][j] = acc;
    }
    if (tid < 96) {
        int j = tid / 3, cc = tid - (tid/3)*3;
        float cx = spx[j]*128.f - 0.5f, cy = spy[j]*128.f - 0.5f;
        float cx0f = floorf(cx), cy0f = floorf(cy);
        int x0 = (int)cx0f, y0 = (int)cy0f;
        float wx1 = cx - cx0f, wy1 = cy - cy0f;
        const float* p = coarse + (size_t)(n*NCLS + cc)*CH*CH;
        float acc = 0.f;
        if (x0 >= 0   && y0 >= 0  ) acc += (1.f-wx1)*(1.f-wy1)*p[y0*CH + x0];
        if (x0+1 < CH && y0 >= 0  ) acc += wx1*(1.f-wy1)*p[y0*CH + x0+1];
        if (x0 >= 0   && y0+1 < CH) acc += (1.f-wx1)*wy1*p[(y0+1)*CH + x0];
        if (x0+1 < CH && y0+1 < CH) acc += wx1*wy1*p[(y0+1)*CH + x0+1];
        tile[NIN + cc][j] = acc;
    }
    __syncthreads();
    for (int idx = tid; idx < KIN*32; idx += 128) {
        int r = idx >> 5, j = idx & 31;
        float vv = tile[r][j];
        g_Xa[(size_t)r*PTOT + pBase + j] = vv;
        if (r >= NIN) g_Xb[(size_t)r*PTOT + pBase + j] = vv;   // coarse rows live in both buffers
    }
}

// ---------------- FC layer: Y[0:128] = relu(W(128x131) @ X[0:131] + b), tile 128 outs x 128 pts ----------------
#define WS_STRIDE 129
#define WS_FLOATS 16900            // 131*129 = 16899, padded to multiple of 4 for float4 Xs
__global__ void fc_kernel(const float* __restrict__ X, float* __restrict__ Y,
                          const float* __restrict__ W, const float* __restrict__ B) {
    extern __shared__ float sm[];
    float* Ws = sm;                // [131][129] (stride 129: conflict-free transposed store)
    float* Xs = sm + WS_FLOATS;    // [131][128]
    int tid = threadIdx.x;         // 256
    int pBase = blockIdx.x * 128;
    for (int idx = tid; idx < NIN*KIN; idx += 256) {
        int m = idx / KIN, k = idx - m*KIN;
        Ws[k*WS_STRIDE + m] = W[idx];
    }
    for (int idx = tid; idx < KIN*128; idx += 256) {
        int k = idx >> 7, p = idx & 127;
        Xs[idx] = X[(size_t)k*PTOT + pBase + p];
    }
    __syncthreads();
    int p0 = (tid & 15) << 3;
    int o0 = (tid >> 4) << 3;
    float acc[8][8];
    #pragma unroll
    for (int o = 0; o < 8; o++)
        #pragma unroll
        for (int p = 0; p < 8; p++) acc[o][p] = 0.f;
    for (int k = 0; k < KIN; k++) {
        float wv[8];
        #pragma unroll
        for (int j = 0; j < 8; j++) wv[j] = Ws[k*WS_STRIDE + o0 + j];
        float4 xA = *(const float4*)&Xs[(k << 7) + p0];
        float4 xB = *(const float4*)&Xs[(k << 7) + p0 + 4];
        float xv[8] = {xA.x, xA.y, xA.z, xA.w, xB.x, xB.y, xB.z, xB.w};
        #pragma unroll
        for (int o = 0; o < 8; o++)
            #pragma unroll
            for (int p = 0; p < 8; p++) acc[o][p] += wv[o]*xv[p];
    }
    #pragma unroll
    for (int o = 0; o < 8; o++) {
        float bo = __ldg(&B[o0 + o]);
        #pragma unroll
        for (int p = 0; p < 8; p++)
            Y[(size_t)(o0+o)*PTOT + pBase + p0 + p] = fmaxf(acc[o][p] + bo, 0.f);
    }
}

// ---------------- head (131 -> 3) + scatter into sem ----------------
__global__ void head_scatter(const float* __restrict__ X, const float* __restrict__ wp,
                             const float* __restrict__ bp, float* __restrict__ sem, int HW) {
    __shared__ float wps[NCLS*KIN];
    __shared__ float bps[NCLS];
    int tid = threadIdx.x;
    for (int i = tid; i < NCLS*KIN; i += 256) wps[i] = wp[i];
    if (tid < NCLS) bps[tid] = bp[tid];
    __syncthreads();
    int p = blockIdx.x*256 + tid;
    float a0 = 0.f, a1 = 0.f, a2 = 0.f;
    for (int k = 0; k < KIN; k++) {
        float xv = X[(size_t)k*PTOT + p];
        a0 += wps[k]*xv;
        a1 += wps[KIN + k]*xv;
        a2 += wps[2*KIN + k]*xv;
    }
    int n = p >> 13;
    int id = g_idx[p];
    sem[(size_t)(n*NCLS + 0)*HW + id] = a0 + bps[0];
    sem[(size_t)(n*NCLS + 1)*HW + id] = a1 + bps[1];
    sem[(size_t)(n*NCLS + 2)*HW + id] = a2 + bps[2];
}

// ---------------- launch ----------------
extern "C" void kernel_launch(void* const* d_in, const int* in_sizes, int n_in,
                              void* d_out, int out_size) {
    const float* coarse = (const float*)d_in[0];
    const float* feat   = (const float*)d_in[1];
    const float* w1 = (const float*)d_in[2];
    const float* b1 = (const float*)d_in[3];
    const float* w2 = (const float*)d_in[4];
    const float* b2 = (const float*)d_in[5];
    const float* w3 = (const float*)d_in[6];
    const float* b3 = (const float*)d_in[7];
    const float* wp = (const float*)d_in[8];
    const float* bp = (const float*)d_in[9];
    float* out = (float*)d_out;

    float *sem256, *Xa, *Xb;
    cudaGetSymbolAddress((void**)&sem256, g_sem256);
    cudaGetSymbolAddress((void**)&Xa, g_Xa);
    cudaGetSymbolAddress((void**)&Xb, g_Xb);

    const int FCSMEM = (WS_FLOATS + KIN*128) * 4;   // 134,672 B
    cudaFuncSetAttribute(fc_kernel, cudaFuncAttributeMaxDynamicSharedMemorySize, FCSMEM);

    transpose_kernel<<<dim3(2048, 4, 4), dim3(32, 8)>>>(feat);

    for (int step = 0; step < 2; step++) {
        int Hin = (step == 0) ? 128 : 256;
        int HW  = (2*Hin)*(2*Hin);
        const float* semIn = (step == 0) ? coarse : sem256;
        float* semOut      = (step == 0) ? sem256 : out;

        upsample_unc<<<(NB*HW + 255)/256, 256>>>(semIn, semOut, Hin);

        select_init<<<256, 256>>>();
        for (int pass = 0; pass < 4; pass++) {
            hist_kernel<<<dim3(128, NB), 256>>>(pass, HW);
            resolve_kernel<<<NB, 256>>>(pass);
        }
        select_kernel<<<dim3(128, NB), 256>>>(HW);

        gather_kernel<<<PTOT/32, 128>>>(coarse, 2*Hin);

        fc_kernel<<<PTOT/128, 256, FCSMEM>>>(Xa, Xb, w1, b1);
        fc_kernel<<<PTOT/128, 256, FCSMEM>>>(Xb, Xa, w2, b2);
        fc_kernel<<<PTOT/128, 256, FCSMEM>>>(Xa, Xb, w3, b3);

        head_scatter<<<PTOT/256, 256>>>(Xb, wp, bp, semOut, HW);
    }
}

// round 2
// speedup vs baseline: 2.2469x; 2.2469x over previous
#include <cuda_runtime.h>
#include <math.h>

#define NB   4
#define NCLS 3
#define FH   256       // feature H=W
#define CH   128       // coarse H=W
#define NIN  128
#define KIN  131
#define FCK  144       // KIN padded to 9*16
#define NCH  9         // k-chunks of 16
#define PPB  8192
#define PTOT 32768
#define KEYSTRIDE 262144
#define TOPK 8192u

// ---------------- scratch ----------------
__device__ float        g_featT[(size_t)NB*FH*FH*NIN];   // NHWC features
__device__ float        g_sem256[NB*NCLS*256*256];
__device__ unsigned int g_keys[NB*KEYSTRIDE];
__device__ unsigned int g_hist2[NB*4096];
__device__ int          g_bstar[NB];
__device__ int          g_kRem[NB];
__device__ int          g_selCount[NB];
__device__ int          g_candCount[NB];
__device__ unsigned long long g_cand[(size_t)NB*KEYSTRIDE];
__device__ int          g_idx[PTOT];
__device__ float        g_Xa[(size_t)FCK*PTOT];
__device__ float        g_Xb[(size_t)FCK*PTOT];
__device__ float2       g_Wd[(size_t)3*FCK*NIN];         // dup-packed transposed weights

__device__ __forceinline__ unsigned int fkey(float f) {
    unsigned int u = __float_as_uint(f);
    return (u & 0x80000000u) ? ~u : (u | 0x80000000u);
}
__device__ __forceinline__ unsigned long long ffma2(unsigned long long a, unsigned long long b, unsigned long long c) {
    unsigned long long d;
    asm("fma.rn.f32x2 %0, %1, %2, %3;" : "=l"(d) : "l"(a), "l"(b), "l"(c));
    return d;
}
__device__ __forceinline__ void unpack2(unsigned long long v, float& lo, float& hi) {
    unsigned int a, b;
    asm("mov.b64 {%0,%1}, %2;" : "=r"(a), "=r"(b) : "l"(v));
    lo = __uint_as_float(a); hi = __uint_as_float(b);
}

// ---------------- one-time init: zero pad rows + histograms ----------------
__global__ void init_pads() {
    int i = blockIdx.x*blockDim.x + threadIdx.x;
    int stride = gridDim.x*blockDim.x;
    const int PADN = (FCK-KIN)*PTOT;
    for (int j = i; j < PADN; j += stride) {
        g_Xa[(size_t)KIN*PTOT + j] = 0.f;
        g_Xb[(size_t)KIN*PTOT + j] = 0.f;
    }
    for (int j = i; j < NB*4096; j += stride) g_hist2[j] = 0;
}

// ---------------- weight prep: transpose + dup-pack + zero-pad ----------------
__global__ void wprep(const float* __restrict__ w1, const float* __restrict__ w2, const float* __restrict__ w3) {
    int i = blockIdx.x*blockDim.x + threadIdx.x;   // < 3*FCK*NIN
    if (i >= 3*FCK*NIN) return;
    int l = i / (FCK*NIN); int r = i - l*(FCK*NIN);
    int k = r >> 7; int o = r & 127;
    const float* w = (l == 0) ? w1 : ((l == 1) ? w2 : w3);
    float v = (k < KIN) ? w[o*KIN + k] : 0.f;
    g_Wd[i] = make_float2(v, v);
}

// ---------------- features NCHW -> NHWC ----------------
__global__ void transpose_kernel(const float* __restrict__ f) {
    __shared__ float tile[32][33];
    int n = blockIdx.z;
    int pix0 = blockIdx.x * 32;
    int c0   = blockIdx.y * 32;
    int tx = threadIdx.x, ty = threadIdx.y;
    #pragma unroll
    for (int i = ty; i < 32; i += 8)
        tile[i][tx] = f[(size_t)(n*NIN + c0 + i)*(FH*FH) + pix0 + tx];
    __syncthreads();
    #pragma unroll
    for (int i = ty; i < 32; i += 8)
        g_featT[(size_t)(n*(FH*FH) + pix0 + i)*NIN + c0 + tx] = tile[tx][i];
}

// ---------------- fused 2x upsample + uncertainty key + 4096-bin histogram ----------------
__global__ void upsample_unc_hist(const float* __restrict__ in, float* __restrict__ out, int Hin) {
    __shared__ unsigned int sh[4096];
    int n = blockIdx.y;
    for (int i = threadIdx.x; i < 4096; i += blockDim.x) sh[i] = 0;
    __syncthreads();
    int W = 2*Hin, HW = W*W;
    for (int pix = blockIdx.x*blockDim.x + threadIdx.x; pix < HW; pix += gridDim.x*blockDim.x) {
        int y = pix / W;  int x = pix - y*W;
        int y0 = (y - 1) >> 1, x0 = (x - 1) >> 1;
        float wy1 = (y & 1) ? 0.25f : 0.75f;
        float wx1 = (x & 1) ? 0.25f : 0.75f;
        int y1 = y0 + 1, x1 = x0 + 1;
        int xa = (x0 < 0) ? 0 : x0;
        int xb = (x1 > Hin-1) ? Hin-1 : x1;
        float v[NCLS];
        #pragma unroll
        for (int c = 0; c < NCLS; c++) {
            const float* p = in + (size_t)(n*NCLS + c)*Hin*Hin;
            float colA, colB;
            if (y0 < 0)            { colA = p[xa];               colB = p[xb]; }
            else if (y1 > Hin - 1) { colA = p[(Hin-1)*Hin + xa]; colB = p[(Hin-1)*Hin + xb]; }
            else {
                colA = (1.f - wy1)*p[y0*Hin + xa] + wy1*p[y1*Hin + xa];
                colB = (1.f - wy1)*p[y0*Hin + xb] + wy1*p[y1*Hin + xb];
            }
            float vv;
            if (x0 < 0)            vv = colA;
            else if (x1 > Hin - 1) vv = colB;
            else                   vv = (1.f - wx1)*colA + wx1*colB;
            v[c] = vv;
            out[(size_t)(n*NCLS + c)*HW + pix] = vv;
        }
        float hi = fmaxf(v[0], v[1]), lo = fminf(v[0], v[1]);
        float m1 = fmaxf(hi, v[2]);
        float m2 = fmaxf(lo, fminf(hi, v[2]));
        unsigned int key = fkey(m2 - m1);
        g_keys[n*KEYSTRIDE + pix] = key;
        atomicAdd(&sh[key >> 20], 1u);
    }
    __syncthreads();
    for (int i = threadIdx.x; i < 4096; i += blockDim.x) {
        unsigned int v = sh[i];
        if (v) atomicAdd(&g_hist2[n*4096 + i], v);
    }
}

// ---------------- resolve threshold bucket (1 block/batch, 1024 thr) ----------------
__global__ void resolve4k() {
    int n = blockIdx.x, t = threadIdx.x;
    unsigned int* hist = g_hist2 + n*4096;
    __shared__ unsigned int s[1024];
    unsigned int h[4];
    int base = 4095 - 4*t;
    unsigned int sum = 0;
    #pragma unroll
    for (int j = 0; j < 4; j++) { h[j] = hist[base - j]; sum += h[j]; }
    s[t] = sum;
    __syncthreads();
    for (int off = 1; off < 1024; off <<= 1) {
        unsigned int v = (t >= off) ? s[t - off] : 0u;
        __syncthreads();
        s[t] += v;
        __syncthreads();
    }
    unsigned int incl = s[t], excl = incl - sum;
    if (excl < TOPK && TOPK <= incl) {
        unsigned int c = excl;
        #pragma unroll
        for (int j = 0; j < 4; j++) {
            if (c + h[j] >= TOPK) { g_bstar[n] = base - j; g_kRem[n] = (int)(TOPK - c); break; }
            c += h[j];
        }
    }
    __syncthreads();
    for (int i = t; i < 4096; i += 1024) hist[i] = 0;   // clean for next step
    if (t == 0) { g_selCount[n] = 0; g_candCount[n] = 0; }
}

// ---------------- compact: definite winners -> g_idx; threshold bucket -> candidates ----------------
__global__ void compact_kernel(int HW) {
    int n = blockIdx.y;
    int bstar = g_bstar[n];
    int stride = gridDim.x*blockDim.x;
    for (int i = blockIdx.x*blockDim.x + threadIdx.x; i < HW; i += stride) {
        unsigned int key = g_keys[n*KEYSTRIDE + i];
        int b = (int)(key >> 20);
        if (b > bstar) {
            int p = atomicAdd(&g_selCount[n], 1);
            g_idx[n*PPB + p] = i;
        } else if (b == bstar) {
            int p = atomicAdd(&g_candCount[n], 1);
            g_cand[(size_t)n*KEYSTRIDE + p] = ((unsigned long long)key << 32) | (unsigned int)(~(unsigned int)i);
        }
    }
}

// ---------------- exact select among candidates (1 block/batch) ----------------
__global__ void candsel() {
    int n = blockIdx.x, t = threadIdx.x;  // 1024 threads
    __shared__ unsigned int hist[2048];
    __shared__ unsigned int sc[1024];
    __shared__ int sh_d;
    __shared__ unsigned int sh_sub;
    int m = g_candCount[n];
    int need = g_kRem[n];
    const unsigned long long* cand = g_cand + (size_t)n*KEYSTRIDE;
    unsigned long long prefix = 0, pmask = 0;
    if (m > need) {
        const int shifts[6] = {53, 42, 31, 20, 9, 0};
        for (int pass = 0; pass < 6; pass++) {
            int shift = shifts[pass];
            for (int i = t; i < 2048; i += 1024) hist[i] = 0;
            __syncthreads();
            for (int i = t; i < m; i += 1024) {
                unsigned long long c = cand[i];
                if ((c & pmask) == prefix)
                    atomicAdd(&hist[(unsigned int)(c >> shift) & 0x7FFu], 1u);
            }
            __syncthreads();
            unsigned int a = hist[2047 - 2*t], b = hist[2046 - 2*t];
            sc[t] = a + b;
            __syncthreads();
            for (int off = 1; off < 1024; off <<= 1) {
                unsigned int v = (t >= off) ? sc[t - off] : 0u;
                __syncthreads();
                sc[t] += v;
                __syncthreads();
            }
            unsigned int incl = sc[t], excl = incl - (a + b);
            unsigned int un = (unsigned int)need;
            if (excl < un && un <= incl) {
                if (excl + a >= un) { sh_d = 2047 - 2*t; sh_sub = excl; }
                else                { sh_d = 2046 - 2*t; sh_sub = excl + a; }
            }
            __syncthreads();
            need -= (int)sh_sub;
            prefix |= ((unsigned long long)(unsigned int)sh_d) << shift;
            pmask  |= 0x7FFull << shift;
            __syncthreads();
        }
    } else {
        prefix = 0;   // select all candidates
    }
    for (int i = t; i < m; i += 1024) {
        unsigned long long c = cand[i];
        if (c >= prefix) {
            int p = atomicAdd(&g_selCount[n], 1);
            g_idx[n*PPB + p] = (int)(~(unsigned int)(c & 0xFFFFFFFFull));
        }
    }
}

// ---------------- gather: bilinear sample features (NHWC) + coarse -> X [131][PTOT] ----------------
__global__ void gather_kernel(const float* __restrict__ coarse, int gridW) {
    __shared__ float tile[KIN][33];
    __shared__ int   sx0[32], sy0[32];
    __shared__ float sw0[32], sw1[32], sw2[32], sw3[32];
    __shared__ float spx[32], spy[32];
    int pBase = blockIdx.x * 32;
    int tid = threadIdx.x;              // 128
    int n = pBase >> 13;
    if (tid < 32) {
        int id = g_idx[pBase + tid];
        float px = ((float)(id % gridW) + 0.5f) / (float)gridW;
        float py = ((float)(id / gridW) + 0.5f) / (float)gridW;
        spx[tid] = px; spy[tid] = py;
        float fx = px * 256.f - 0.5f, fy = py * 256.f - 0.5f;
        float fx0 = floorf(fx), fy0 = floorf(fy);
        float wx1 = fx - fx0, wy1 = fy - fy0;
        sx0[tid] = (int)fx0; sy0[tid] = (int)fy0;
        sw0[tid] = (1.f-wx1)*(1.f-wy1);
        sw1[tid] = wx1*(1.f-wy1);
        sw2[tid] = (1.f-wx1)*wy1;
        sw3[tid] = wx1*wy1;
    }
    __syncthreads();
    int c = tid;
    const float* base = g_featT + (size_t)n*FH*FH*NIN;
    #pragma unroll 4
    for (int j = 0; j < 32; j++) {
        int x0 = sx0[j], y0 = sy0[j];
        float acc = 0.f;
        if (x0 >= 0   && y0 >= 0  ) acc += sw0[j]*base[((y0  )*FH + x0  )*NIN + c];
        if (x0+1 < FH && y0 >= 0  ) acc += sw1[j]*base[((y0  )*FH + x0+1)*NIN + c];
        if (x0 >= 0   && y0+1 < FH) acc += sw2[j]*base[((y0+1)*FH + x0  )*NIN + c];
        if (x0+1 < FH && y0+1 < FH) acc += sw3[j]*base[((y0+1)*FH + x0+1)*NIN + c];
        tile[c][j] = acc;
    }
    if (tid < 96) {
        int j = tid / 3, cc = tid - (tid/3)*3;
        float cx = spx[j]*128.f - 0.5f, cy = spy[j]*128.f - 0.5f;
        float cx0f = floorf(cx), cy0f = floorf(cy);
        int x0 = (int)cx0f, y0 = (int)cy0f;
        float wx1 = cx - cx0f, wy1 = cy - cy0f;
        const float* p = coarse + (size_t)(n*NCLS + cc)*CH*CH;
        float acc = 0.f;
        if (x0 >= 0   && y0 >= 0  ) acc += (1.f-wx1)*(1.f-wy1)*p[y0*CH + x0];
        if (x0+1 < CH && y0 >= 0  ) acc += wx1*(1.f-wy1)*p[y0*CH + x0+1];
        if (x0 >= 0   && y0+1 < CH) acc += (1.f-wx1)*wy1*p[(y0+1)*CH + x0];
        if (x0+1 < CH && y0+1 < CH) acc += wx1*wy1*p[(y0+1)*CH + x0+1];
        tile[NIN + cc][j] = acc;
    }
    __syncthreads();
    for (int idx = tid; idx < KIN*32; idx += 128) {
        int r = idx >> 5, j = idx & 31;
        float vv = tile[r][j];
        g_Xa[(size_t)r*PTOT + pBase + j] = vv;
        if (r >= NIN) g_Xb[(size_t)r*PTOT + pBase + j] = vv;
    }
}

// ---------------- FC layer via fma.rn.f32x2: Y = relu(W @ X + b) ----------------
__global__ void __launch_bounds__(256, 2)
fc_kernel(const float* __restrict__ X, float* __restrict__ Y,
          const float2* __restrict__ Wd, const float* __restrict__ B) {
    __shared__ float2 Wbuf[2][16*128];   // dup pairs [kk][o]
    __shared__ float  Xbuf[2][16*128];   // [kk][p]
    int tid = threadIdx.x;
    int pBase = blockIdx.x * 128;

    // stage chunk 0
    {
        const float4* wg = (const float4*)(Wd);
        float4* wdst = (float4*)Wbuf[0];
        #pragma unroll
        for (int q = 0; q < 4; q++) wdst[tid + 256*q] = wg[tid + 256*q];
        float4* xdst = (float4*)Xbuf[0];
        #pragma unroll
        for (int q = 0; q < 2; q++) {
            int f = tid + 256*q;
            int kk = f >> 5, c4 = f & 31;
            xdst[f] = *(const float4*)(X + (size_t)kk*PTOT + pBase + (c4 << 2));
        }
    }
    __syncthreads();

    int o0 = (tid >> 4) << 3;
    int p0 = (tid & 15) << 3;
    unsigned long long acc[8][4];
    #pragma unroll
    for (int o = 0; o < 8; o++)
        #pragma unroll
        for (int j = 0; j < 4; j++) acc[o][j] = 0ull;

    float4 wpre[4], xpre[2];
    for (int cch = 0; cch < NCH; cch++) {
        int cur = cch & 1;
        if (cch < NCH-1) {
            const float4* wg = (const float4*)(Wd + (size_t)(cch+1)*2048);
            #pragma unroll
            for (int q = 0; q < 4; q++) wpre[q] = wg[tid + 256*q];
            #pragma unroll
            for (int q = 0; q < 2; q++) {
                int f = tid + 256*q;
                int kk = f >> 5, c4 = f & 31;
                xpre[q] = *(const float4*)(X + (size_t)((cch+1)*16 + kk)*PTOT + pBase + (c4 << 2));
            }
        }
        #pragma unroll
        for (int kk = 0; kk < 16; kk++) {
            const ulonglong2* wrow = (const ulonglong2*)&Wbuf[cur][kk*128 + o0];
            const ulonglong2* xrow = (const ulonglong2*)&Xbuf[cur][kk*128 + p0];
            ulonglong2 w01 = wrow[0], w23 = wrow[1], w45 = wrow[2], w67 = wrow[3];
            ulonglong2 xA = xrow[0], xB = xrow[1];
            unsigned long long w[8] = {w01.x, w01.y, w23.x, w23.y, w45.x, w45.y, w67.x, w67.y};
            unsigned long long x[4] = {xA.x, xA.y, xB.x, xB.y};
            #pragma unroll
            for (int o = 0; o < 8; o++)
                #pragma unroll
                for (int j = 0; j < 4; j++)
                    acc[o][j] = ffma2(w[o], x[j], acc[o][j]);
        }
        if (cch < NCH-1) {
            __syncthreads();
            int nb = (cch+1) & 1;
            float4* wdst = (float4*)Wbuf[nb];
            #pragma unroll
            for (int q = 0; q < 4; q++) wdst[tid + 256*q] = wpre[q];
            float4* xdst = (float4*)Xbuf[nb];
            #pragma unroll
            for (int q = 0; q < 2; q++) xdst[tid + 256*q] = xpre[q];
            __syncthreads();
        }
    }

    #pragma unroll
    for (int o = 0; o < 8; o++) {
        float bo = __ldg(&B[o0 + o]);
        float r[8];
        #pragma unroll
        for (int j = 0; j < 4; j++) unpack2(acc[o][j], r[2*j], r[2*j+1]);
        float4 outA, outB;
        outA.x = fmaxf(r[0]+bo, 0.f); outA.y = fmaxf(r[1]+bo, 0.f);
        outA.z = fmaxf(r[2]+bo, 0.f); outA.w = fmaxf(r[3]+bo, 0.f);
        outB.x = fmaxf(r[4]+bo, 0.f); outB.y = fmaxf(r[5]+bo, 0.f);
        outB.z = fmaxf(r[6]+bo, 0.f); outB.w = fmaxf(r[7]+bo, 0.f);
        *(float4*)(Y + (size_t)(o0+o)*PTOT + pBase + p0)     = outA;
        *(float4*)(Y + (size_t)(o0+o)*PTOT + pBase + p0 + 4) = outB;
    }
}

// ---------------- head (131 -> 3) + scatter ----------------
__global__ void head_scatter(const float* __restrict__ X, const float* __restrict__ wp,
                             const float* __restrict__ bp, float* __restrict__ sem, int HW) {
    __shared__ float wps[NCLS*KIN];
    __shared__ float bps[NCLS];
    int tid = threadIdx.x;
    for (int i = tid; i < NCLS*KIN; i += 256) wps[i] = wp[i];
    if (tid < NCLS) bps[tid] = bp[tid];
    __syncthreads();
    int p = blockIdx.x*256 + tid;
    float a0 = 0.f, a1 = 0.f, a2 = 0.f;
    for (int k = 0; k < KIN; k++) {
        float xv = X[(size_t)k*PTOT + p];
        a0 += wps[k]*xv;
        a1 += wps[KIN + k]*xv;
        a2 += wps[2*KIN + k]*xv;
    }
    int n = p >> 13;
    int id = g_idx[p];
    sem[(size_t)(n*NCLS + 0)*HW + id] = a0 + bps[0];
    sem[(size_t)(n*NCLS + 1)*HW + id] = a1 + bps[1];
    sem[(size_t)(n*NCLS + 2)*HW + id] = a2 + bps[2];
}

// ---------------- launch ----------------
extern "C" void kernel_launch(void* const* d_in, const int* in_sizes, int n_in,
                              void* d_out, int out_size) {
    const float* coarse = (const float*)d_in[0];
    const float* feat   = (const float*)d_in[1];
    const float* w1 = (const float*)d_in[2];
    const float* b1 = (const float*)d_in[3];
    const float* w2 = (const float*)d_in[4];
    const float* b2 = (const float*)d_in[5];
    const float* w3 = (const float*)d_in[6];
    const float* b3 = (const float*)d_in[7];
    const float* wp = (const float*)d_in[8];
    const float* bp = (const float*)d_in[9];
    float* out = (float*)d_out;

    float *sem256, *Xa, *Xb;
    float2* Wd;
    cudaGetSymbolAddress((void**)&sem256, g_sem256);
    cudaGetSymbolAddress((void**)&Xa, g_Xa);
    cudaGetSymbolAddress((void**)&Xb, g_Xb);
    cudaGetSymbolAddress((void**)&Wd, g_Wd);

    init_pads<<<512, 256>>>();
    wprep<<<(3*FCK*NIN + 255)/256, 256>>>(w1, w2, w3);
    transpose_kernel<<<dim3(2048, 4, 4), dim3(32, 8)>>>(feat);

    for (int step = 0; step < 2; step++) {
        int Hin = (step == 0) ? 128 : 256;
        int HW  = (2*Hin)*(2*Hin);
        const float* semIn = (step == 0) ? coarse : sem256;
        float* semOut      = (step == 0) ? sem256 : out;

        upsample_unc_hist<<<dim3(64, NB), 256>>>(semIn, semOut, Hin);
        resolve4k<<<NB, 1024>>>();
        compact_kernel<<<dim3(64, NB), 256>>>(HW);
        candsel<<<NB, 1024>>>();

        gather_kernel<<<PTOT/32, 128>>>(coarse, 2*Hin);

        fc_kernel<<<PTOT/128, 256>>>(Xa, Xb, Wd,              b1);
        fc_kernel<<<PTOT/128, 256>>>(Xb, Xa, Wd + FCK*NIN,    b2);
        fc_kernel<<<PTOT/128, 256>>>(Xa, Xb, Wd + 2*FCK*NIN,  b3);

        head_scatter<<<PTOT/256, 256>>>(Xb, wp, bp, semOut, HW);
    }
}